// round 10
// baseline (speedup 1.0000x reference)
#include <cuda_runtime.h>
#include <cstdint>

// Problem constants (from reference_code)
#define DD    14
#define KK    2
#define BB    512
#define FF    512
#define NT    512
#define NF    1024
#define CELLS (BB * FF)          // 262144 (b,f) cells
#define PIX   (DD * DD)          // 196 pixels per cell
#define CPB   64                 // cells per block
#define THREADS 256
#define STRIDE 34                // float2 per cell: ex[pos 0..15] ey[16..31] pad[2]
                                 // = 17 x 16B chunks; 17 odd -> conflict-free 128b ops

__device__ __forceinline__ float ex2(float a) {
    float r;
    asm("ex2.approx.ftz.f32 %0, %1;" : "=f"(r) : "f"(a));
    return r;
}

// Block handles 64 consecutive (b,f) cells.
//
// ex table uses a 4x4-TRANSPOSED layout: entry for row is stored at position
// (row%4)*4 + row/4. A phase-2 lane (row-subgroup ri) then finds all four of
// its rows (ri, 4+ri, 8+ri, 12+ri) at positions 4ri..4ri+3 = 32 contiguous
// bytes -> TWO LDS.128 before the round loop; rounds are pure FMA + STG.
// ey table stays linear (entries 0..13; 14,15 pad).
//
// Phase 1 (ALL 256 threads): thread (hf, axis, cell) computes 8 table entries
//   directly (a = lp2 - (row-c)^2 * s2, ex2) and writes them pairwise as
//   conflict-free STS.128. Pad rows 14/15 are written with garbage (never used).
// Phase 2 (8 warps x 8 cells): lane l<28 -> (ri=l/7, jp=l%7) owns pixel
//   columns (2jp, 2jp+1) on rows 4r+ri; streaming STG.64 per round.
__global__ __launch_bounds__(THREADS, 7) void gaussian_spot_kernel(
    const float* __restrict__ height,      // [K,B,F]
    const float* __restrict__ width,       // [K,B,F]
    const float* __restrict__ x,           // [K,B,F]
    const float* __restrict__ y,           // [K,B,F]
    const float* __restrict__ background,  // [B,F]
    const float* __restrict__ target_locs, // [NT,NF,2]
    const int*   __restrict__ n_idx,       // [B,1]
    const int*   __restrict__ f_arr,       // [F]
    float*       __restrict__ out)         // [1,B,F,D,D]
{
    __shared__ __align__(16) float2 tab[CPB * STRIDE];   // 17408 B
    __shared__ float bgs[CPB];

    const int t = threadIdx.x;
    const int blockbase = blockIdx.x * CPB;

    // ---------------- Phase 1: build tables (all 256 threads) --------------
    {
        const int lc   = t & (CPB - 1);   // 0..63
        const int sub  = t >> 6;          // 0..3
        const int axis = sub & 1;         // 0 = x/i-axis (ex), 1 = y/j-axis (ey)
        const int hf   = sub >> 1;        // positions [8*hf, 8*hf+8)
        const int cell = blockbase + lc;
        const int b = cell >> 9;          // / FF
        const int f = cell & (FF - 1);

        const int n  = n_idx[b];          // broadcast within block
        const int fi = f_arr[f];          // coalesced
        const float cloc = target_locs[((size_t)n * NF + (size_t)fi) * 2 + axis];
        if (sub == 0) bgs[lc] = background[cell];   // coalesced, once

        float c[KK], s2[KK], lp2[KK];
#pragma unroll
        for (int k = 0; k < KK; k++) {
            const int off = k * CELLS + cell;        // coalesced loads
            const float h  = height[off];
            const float w  = width[off];
            const float sh = axis ? y[off] : x[off];
            c[k] = cloc + sh;                        // spot center on this axis
            const float w2    = w * w;
            const float invw2 = __fdividef(1.0f, w2);
            s2[k] = 0.72134752044f * invw2;          // log2e / (2 w^2)
            lp2[k] = axis ? 0.0f
                          : __log2f(h * 0.15915494309f * invw2);
        }

        float2* trow = tab + lc * STRIDE + axis * 16 + (hf << 3);
#pragma unroll
        for (int dd = 0; dd < 8; dd += 2) {
            const int p0 = (hf << 3) + dd;
            const int p1 = p0 + 1;
            // ex: transposed position -> row; ey: linear (compile-time consts)
            const int r0 = axis ? p0 : ((p0 & 3) * 4 + (p0 >> 2));
            const int r1 = axis ? p1 : ((p1 & 3) * 4 + (p1 >> 2));
            float e[4];
#pragma unroll
            for (int k = 0; k < KK; k++) {
                const float dc0 = (float)r0 - c[k];
                const float dc1 = (float)r1 - c[k];
                e[k]     = ex2(fmaf(-dc0, dc0 * s2[k], lp2[k]));
                e[2 + k] = ex2(fmaf(-dc1, dc1 * s2[k], lp2[k]));
            }
            *reinterpret_cast<float4*>(trow + dd)
                = make_float4(e[0], e[1], e[2], e[3]);   // conflict-free STS.128
        }
    }
    __syncthreads();

    // ---------------- Phase 2: emit pixels (8 warps x 8 cells each) --------
    const int warp = t >> 5;
    const int lane = t & 31;

    const bool active = lane < 28;
    const int  ls = active ? lane : 0;    // clamp idle lanes to safe indices
    const int  ri = ls / 7;               // row-subgroup 0..3
    const int  jp = ls - ri * 7;          // pair column 0..6

#pragma unroll
    for (int cc = 0; cc < 8; cc++) {
        const int lc = warp * 8 + cc;
        const float4* cexq = reinterpret_cast<const float4*>(tab + lc * STRIDE);

        // All four rounds' ex pairs: positions 4ri..4ri+3 (32B, two LDS.128).
        const float4 exA = cexq[2 * ri];        // rounds 0,1: {x0,x1 | y0,y1}... (spot0,spot1 pairs)
        const float4 exB = cexq[2 * ri + 1];    // rounds 2,3
        // Round-invariant ey: cey entries 2jp, 2jp+1 (one LDS.128).
        const float4 eyq = *reinterpret_cast<const float4*>(tab + lc * STRIDE + 16 + 2 * jp);
        const float  bg  = bgs[lc];
        float* outp = out + (size_t)(blockbase + lc) * PIX;

#pragma unroll
        for (int r = 0; r < 4; r++) {
            const float ex0 = (r == 0) ? exA.x : (r == 1) ? exA.z : (r == 2) ? exB.x : exB.z;
            const float ex1 = (r == 0) ? exA.y : (r == 1) ? exA.w : (r == 2) ? exB.y : exB.w;
            float v0 = fmaf(ex1, eyq.y, bg);
            v0       = fmaf(ex0, eyq.x, v0);
            float v1 = fmaf(ex1, eyq.w, bg);
            v1       = fmaf(ex0, eyq.z, v1);
            const int row = 4 * r + ri;           // 14,15 masked below
            if (active && row < DD)
                __stcs(reinterpret_cast<float2*>(outp + row * DD + 2 * jp),
                       make_float2(v0, v1));      // streaming STG.64
        }
    }
}

extern "C" void kernel_launch(void* const* d_in, const int* in_sizes, int n_in,
                              void* d_out, int out_size)
{
    const float* height      = (const float*)d_in[0];
    const float* width       = (const float*)d_in[1];
    const float* x           = (const float*)d_in[2];
    const float* y           = (const float*)d_in[3];
    const float* background  = (const float*)d_in[4];
    const float* target_locs = (const float*)d_in[5];
    const int*   n_idx       = (const int*)d_in[6];
    const int*   f_arr       = (const int*)d_in[7];
    float*       out         = (float*)d_out;

    const int blocks = CELLS / CPB;   // 4096
    gaussian_spot_kernel<<<blocks, THREADS>>>(height, width, x, y, background,
                                              target_locs, n_idx, f_arr, out);
}

// round 11
// speedup vs baseline: 1.0626x; 1.0626x over previous
#include <cuda_runtime.h>
#include <cstdint>

// Problem constants (from reference_code)
#define DD    14
#define KK    2
#define BB    512
#define FF    512
#define NT    512
#define NF    1024
#define CELLS (BB * FF)          // 262144 (b,f) cells
#define PIX   (DD * DD)          // 196 pixels per cell
#define CPB   64                 // cells per block
#define THREADS 256
#define STRIDE 34                // float2 per cell: cex[0..15] cey[16..31] pad[2]
                                 // = 17 x 16B chunks; 17 odd -> conflict-free 128b ops

__device__ __forceinline__ float ex2(float a) {
    float r;
    asm("ex2.approx.ftz.f32 %0, %1;" : "=f"(r) : "f"(a));
    return r;
}

// Block handles 64 consecutive (b,f) cells.
// Phase 1 (ALL 256 threads): thread (hf, axis, cell) builds 8 entries of the
//   14-entry separable exp table (d in [8*hf, 8*hf+8), last 2 masked) for both
//   spots via an incremental log2-space recurrence started at d0.
//   Entries are written pairwise as conflict-free STS.128 (chunk stride 17, odd).
// Phase 2 (8 warps x 8 cells): ROW-PARALLEL lanes. lane l -> (ri=l/7, jp=l%7)
//   owns pixel columns (2jp, 2jp+1) on rows 4r+ri. Lanes 28..31 clamp to
//   lane 0's work: same value, same address -> merged store, NO lane predicate.
//   Stores for r=0..2 are provably in-bounds (row<=13) -> unconditional;
//   only r=3 carries a runtime predicate (ri<2).
__global__ __launch_bounds__(THREADS, 7) void gaussian_spot_kernel(
    const float* __restrict__ height,      // [K,B,F]
    const float* __restrict__ width,       // [K,B,F]
    const float* __restrict__ x,           // [K,B,F]
    const float* __restrict__ y,           // [K,B,F]
    const float* __restrict__ background,  // [B,F]
    const float* __restrict__ target_locs, // [NT,NF,2]
    const int*   __restrict__ n_idx,       // [B,1]
    const int*   __restrict__ f_arr,       // [F]
    float*       __restrict__ out)         // [1,B,F,D,D]
{
    __shared__ __align__(16) float2 tab[CPB * STRIDE];   // 17408 B
    __shared__ float bgs[CPB];

    const int t = threadIdx.x;
    const int blockbase = blockIdx.x * CPB;

    // ---------------- Phase 1: build tables (all 256 threads) --------------
    {
        const int lc   = t & (CPB - 1);   // 0..63
        const int sub  = t >> 6;          // 0..3
        const int axis = sub & 1;         // 0 = x/i-axis (ex), 1 = y/j-axis (ey)
        const int hf   = sub >> 1;        // 0: d=0..7, 1: d=8..13 (+2 masked)
        const int cell = blockbase + lc;
        const int b = cell >> 9;          // / FF
        const int f = cell & (FF - 1);

        const int n  = n_idx[b];          // broadcast within block
        const int fi = f_arr[f];          // coalesced
        const float cloc = target_locs[((size_t)n * NF + (size_t)fi) * 2 + axis];
        if (sub == 0) bgs[lc] = background[cell];   // coalesced, once

        const float d0 = (float)(hf << 3);

        float a[KK], dl[KK], e2[KK];
#pragma unroll
        for (int k = 0; k < KK; k++) {
            const int off = k * CELLS + cell;        // coalesced loads
            const float h  = height[off];
            const float w  = width[off];
            const float sh = axis ? y[off] : x[off];
            const float c  = cloc + sh;              // spot center on this axis
            const float w2    = w * w;
            const float invw2 = __fdividef(1.0f, w2);
            const float s2    = 0.72134752044f * invw2;   // log2e / (2 w^2)
            const float lp2 = axis ? 0.0f
                                   : __log2f(h * 0.15915494309f * invw2);
            const float dc = d0 - c;
            a[k]  = fmaf(-dc, dc * s2, lp2);         // a(d0)
            dl[k] = -(dc + dc + 1.0f) * s2;          // a(d0+1)-a(d0)
            e2[k] = s2 + s2;                         // -(2nd difference)
        }

        float2* trow = tab + lc * STRIDE + axis * 16 + (hf << 3);
#pragma unroll
        for (int dd = 0; dd < 8; dd += 2) {
            const float e00 = ex2(a[0]);
            const float e01 = ex2(a[1]);
            a[0] += dl[0]; dl[0] -= e2[0];
            a[1] += dl[1]; dl[1] -= e2[1];
            const float e10 = ex2(a[0]);
            const float e11 = ex2(a[1]);
            a[0] += dl[0]; dl[0] -= e2[0];
            a[1] += dl[1]; dl[1] -= e2[1];
            if ((hf << 3) + dd < DD)   // masks d=14,15 for hf=1
                *reinterpret_cast<float4*>(trow + dd)
                    = make_float4(e00, e01, e10, e11);   // conflict-free STS.128
        }
    }
    __syncthreads();

    // ---------------- Phase 2: emit pixels (8 warps x 8 cells each) --------
    const int warp = t >> 5;
    const int lane = t & 31;

    const int  ls = (lane < 28) ? lane : 0;  // clamped lanes duplicate lane 0
    const int  ri = ls / 7;                  // row-subgroup 0..3
    const int  jp = ls - ri * 7;             // pair column 0..6
    const bool last_ok = ri < 2;             // r=3 rows 12,13 valid; 14,15 not

#pragma unroll
    for (int cc = 0; cc < 8; cc++) {
        const int lc = warp * 8 + cc;
        const float2* cex = tab + lc * STRIDE;   // ex[i] (prefactor folded)
        const float2* cey = cex + 16;            // ey[j]

        // Round-invariant ey preload: cey[2jp], cey[2jp+1] in one LDS.128.
        // eyq = {ey0[2jp], ey1[2jp], ey0[2jp+1], ey1[2jp+1]}
        const float4 eyq = *reinterpret_cast<const float4*>(cey + 2 * jp);
        const float  bg  = bgs[lc];
        float* outp = out + (size_t)(blockbase + lc) * PIX + 2 * jp;

#pragma unroll
        for (int r = 0; r < 4; r++) {
            const int row = 4 * r + ri;           // <=13 for r<3; 14,15 hit pad
            const float2 exv = cex[row];          // broadcast LDS.64 (pad-safe)
            float v0 = fmaf(exv.y, eyq.y, bg);
            v0       = fmaf(exv.x, eyq.x, v0);
            float v1 = fmaf(exv.y, eyq.w, bg);
            v1       = fmaf(exv.x, eyq.z, v1);
            if (r < 3 || last_ok)                 // compile-time true for r<3
                __stcs(reinterpret_cast<float2*>(outp + row * DD),
                       make_float2(v0, v1));      // streaming STG.64
        }
    }
}

extern "C" void kernel_launch(void* const* d_in, const int* in_sizes, int n_in,
                              void* d_out, int out_size)
{
    const float* height      = (const float*)d_in[0];
    const float* width       = (const float*)d_in[1];
    const float* x           = (const float*)d_in[2];
    const float* y           = (const float*)d_in[3];
    const float* background  = (const float*)d_in[4];
    const float* target_locs = (const float*)d_in[5];
    const int*   n_idx       = (const int*)d_in[6];
    const int*   f_arr       = (const int*)d_in[7];
    float*       out         = (float*)d_out;

    const int blocks = CELLS / CPB;   // 4096
    gaussian_spot_kernel<<<blocks, THREADS>>>(height, width, x, y, background,
                                              target_locs, n_idx, f_arr, out);
}